// round 13
// baseline (speedup 1.0000x reference)
#include <cuda_runtime.h>
#include <cuda_bf16.h>
#include <cstdint>

#define N_NODES 100000
#define N_EDGES 1600000
#define NF      64
#define NG      1024
#define NB      2048
#define NBLK    ((N_NODES + 1023) / 1024)   // 98 scan blocks

// ---------------- scratch (static device globals; no allocation) ----------------
__device__ int   g_deg[N_NODES];
__device__ __align__(16) float g_dinv[N_NODES];
__device__ int   g_rowoff[N_NODES + 1];
__device__ int   g_cursor[N_NODES];
__device__ int   g_bsum[NBLK];
__device__ int   g_boff[NBLK];
__device__ __align__(16) int2  g_csr[N_EDGES];               // (src, w bits)
__device__ __align__(16) __nv_bfloat162 g_aggb[N_NODES * 32]; // agg output (bf16)
__device__ __align__(16) __nv_bfloat162 g_xb [N_NODES * 32];  // x in bf16
__device__ __align__(16) __nv_bfloat162 g_h1b[N_NODES * 32];
__device__ __align__(16) __nv_bfloat162 g_h2b[N_NODES * 32];
__device__ __align__(16) float g_pool[NG * NF];
__device__ int   g_cnt[NG];

__device__ __forceinline__ int clampi(int v, int hi) {
    return v < 0 ? 0 : (v >= hi ? hi - 1 : v);
}

// ---------------- zero + x->bf16 (fused, independent work) ----------------
__global__ void k_zero_xb(const float* __restrict__ x) {
    int i = blockIdx.x * blockDim.x + threadIdx.x;
    int stride = gridDim.x * blockDim.x;
    for (int j = i; j < N_NODES; j += stride) g_deg[j] = 0;
    for (int j = i; j < NG * NF; j += stride) g_pool[j] = 0.0f;
    for (int j = i; j < NG; j += stride) g_cnt[j] = 0;
    const float2* x2 = (const float2*)x;
    for (int j = i; j < N_NODES * 32; j += stride)
        g_xb[j] = __float22bfloat162_rn(x2[j]);
}

// histogram: in-degree over dst (int4 vectorized)
__global__ void k_hist(const int* __restrict__ ei) {
    int i = blockIdx.x * blockDim.x + threadIdx.x;
    int stride = gridDim.x * blockDim.x;
    const int4* dst4 = (const int4*)(ei + N_EDGES);
    for (int e = i; e < N_EDGES / 4; e += stride) {
        int4 d = dst4[e];
        atomicAdd(&g_deg[clampi(d.x, N_NODES)], 1);
        atomicAdd(&g_deg[clampi(d.y, N_NODES)], 1);
        atomicAdd(&g_deg[clampi(d.z, N_NODES)], 1);
        atomicAdd(&g_deg[clampi(d.w, N_NODES)], 1);
    }
}

// ---------------- 3-phase parallel scan over g_deg ----------------
__global__ __launch_bounds__(1024) void k_scan1() {
    __shared__ int ssum[1024];
    int t = threadIdx.x;
    int idx = blockIdx.x * 1024 + t;
    int v = (idx < N_NODES) ? g_deg[idx] : 0;
    ssum[t] = v;
    __syncthreads();
    for (int d = 1; d < 1024; d <<= 1) {
        int u = (t >= d) ? ssum[t - d] : 0;
        __syncthreads();
        ssum[t] += u;
        __syncthreads();
    }
    if (idx < N_NODES) g_rowoff[idx] = ssum[t] - v;   // block-local exclusive
    if (t == 1023) g_bsum[blockIdx.x] = ssum[1023];
}

__global__ void k_scan2() {
    __shared__ int s[128];
    int t = threadIdx.x;
    int v = (t < NBLK) ? g_bsum[t] : 0;
    s[t] = v;
    __syncthreads();
    for (int d = 1; d < 128; d <<= 1) {
        int u = (t >= d) ? s[t - d] : 0;
        __syncthreads();
        s[t] += u;
        __syncthreads();
    }
    if (t < NBLK) g_boff[t] = s[t] - v;
    if (t == 127) g_rowoff[N_NODES] = s[127];
}

__global__ void k_scan3(const int* __restrict__ batch) {   // offsets + dinv + graph counts
    int idx = blockIdx.x * blockDim.x + threadIdx.x;
    if (idx < N_NODES) {
        int off = g_rowoff[idx] + g_boff[idx >> 10];
        g_rowoff[idx] = off;
        g_cursor[idx] = off;
        g_dinv[idx] = rsqrtf((float)g_deg[idx] + 1.0f);
        atomicAdd(&g_cnt[clampi(batch[idx], NG)], 1);
    }
}

__global__ void k_scatter(const int* __restrict__ ei) {
    int i = blockIdx.x * blockDim.x + threadIdx.x;
    int stride = gridDim.x * blockDim.x;
    const int4* src4 = (const int4*)ei;
    const int4* dst4 = (const int4*)(ei + N_EDGES);
    for (int e = i; e < N_EDGES / 4; e += stride) {
        int4 sv = src4[e];
        int4 dv = dst4[e];
#define SCAT(SS, DD)                                                   \
        {                                                              \
            int s = clampi(SS, N_NODES);                               \
            int d = clampi(DD, N_NODES);                               \
            int pos = atomicAdd(&g_cursor[d], 1);                      \
            g_csr[pos] = make_int2(s, __float_as_int(g_dinv[s] * g_dinv[d])); \
        }
        SCAT(sv.x, dv.x) SCAT(sv.y, dv.y) SCAT(sv.z, dv.z) SCAT(sv.w, dv.w)
#undef SCAT
    }
}

// ---------------- aggregation: g_aggb[n] = dinv[n]^2*h[n] + sum_e w_e*h[src_e] ----------------
// one warp per dst node; lane owns features (2*lane, 2*lane+1) as bf16x2; fp32 accum
__global__ __launch_bounds__(256) void k_agg(int src_sel) {
    int warp = (blockIdx.x * blockDim.x + threadIdx.x) >> 5;
    int lane = threadIdx.x & 31;
    if (warp >= N_NODES) return;
    int n = warp;
    const __nv_bfloat162* hb =
        src_sel == 0 ? g_xb : (src_sel == 1 ? g_h1b : g_h2b);
    float dv = g_dinv[n];
    float sn = dv * dv;
    float2 hv = __bfloat1622float2(hb[n * 32 + lane]);
    float accx = sn * hv.x;
    float accy = sn * hv.y;
    int beg = g_rowoff[n];
    int end = g_rowoff[n + 1];
    int j = beg;
    for (; j + 4 <= end; j += 4) {
        int2 e0 = g_csr[j], e1 = g_csr[j + 1], e2 = g_csr[j + 2], e3 = g_csr[j + 3];
        float2 v0 = __bfloat1622float2(hb[e0.x * 32 + lane]);
        float2 v1 = __bfloat1622float2(hb[e1.x * 32 + lane]);
        float2 v2 = __bfloat1622float2(hb[e2.x * 32 + lane]);
        float2 v3 = __bfloat1622float2(hb[e3.x * 32 + lane]);
        float w0 = __int_as_float(e0.y), w1 = __int_as_float(e1.y);
        float w2 = __int_as_float(e2.y), w3 = __int_as_float(e3.y);
        accx += w0 * v0.x + w1 * v1.x + w2 * v2.x + w3 * v3.x;
        accy += w0 * v0.y + w1 * v1.y + w2 * v2.y + w3 * v3.y;
    }
    for (; j < end; j++) {
        int2 e = g_csr[j];
        float2 v = __bfloat1622float2(hb[e.x * 32 + lane]);
        float w = __int_as_float(e.y);
        accx += w * v.x;
        accy += w * v.y;
    }
    g_aggb[n * 32 + lane] = __float22bfloat162_rn(make_float2(accx, accy));
}

// ---------------- tensor-core GEMM: out = agg @ W + b  (bf16 in, fp32 accum) ----
// block = 256 thr (8 warps); warp computes 16 nodes x 64 cols via mma.m16n8k16.
// mode: 0 = ReLU + bf16 store, 2 = pool atomics epilogue
__device__ __forceinline__ void mma16816(float& c0, float& c1, float& c2, float& c3,
                                         uint32_t a0, uint32_t a1, uint32_t a2, uint32_t a3,
                                         uint32_t b0, uint32_t b1) {
    asm volatile(
        "mma.sync.aligned.m16n8k16.row.col.f32.bf16.bf16.f32 "
        "{%0,%1,%2,%3}, {%4,%5,%6,%7}, {%8,%9}, {%0,%1,%2,%3};\n"
        : "+f"(c0), "+f"(c1), "+f"(c2), "+f"(c3)
        : "r"(a0), "r"(a1), "r"(a2), "r"(a3), "r"(b0), "r"(b1));
}

__global__ __launch_bounds__(256) void k_gemm_mma(const float* __restrict__ W,
                                                  const float* __restrict__ b,
                                                  const int* __restrict__ batch,
                                                  int mode, int dst_sel) {
    __shared__ __nv_bfloat16 sA[128 * 72];   // 128 nodes x 64 feats, pitch 72
    __shared__ __nv_bfloat16 sB[64 * 72];    // W^T: sB[n][k], pitch 72
    __shared__ float sbias[64];
    int tid = threadIdx.x;

    // stage W^T (bf16) and bias
    for (int i = tid; i < 64 * 64; i += 256) {
        int k = i >> 6, n = i & 63;
        sB[n * 72 + k] = __float2bfloat16(W[i]);
    }
    if (tid < 64) sbias[tid] = b[tid];

    // stage A tile: 128 node rows x 128B, int4 cooperative
    int node_base = blockIdx.x * 128;
    const int4* src = (const int4*)g_aggb;
    for (int i = tid; i < 128 * 8; i += 256) {
        int row = i >> 3, seg = i & 7;
        int node = node_base + row;
        int4 v = make_int4(0, 0, 0, 0);
        if (node < N_NODES) v = src[node * 8 + seg];
        *(int4*)(sA + row * 72 + seg * 8) = v;   // 144B pitch, 16B aligned
    }
    __syncthreads();

    int warp = tid >> 5, lane = tid & 31;
    int node0 = node_base + warp * 16;
    if (node0 >= N_NODES) return;   // N_NODES % 16 == 0: warps fully valid or invalid
    int g = lane >> 2, ct = lane & 3;

    float c[8][4];
#pragma unroll
    for (int nt = 0; nt < 8; nt++)
#pragma unroll
        for (int q = 0; q < 4; q++) c[nt][q] = 0.f;

    int r0 = warp * 16 + g;
#pragma unroll
    for (int ks = 0; ks < 4; ks++) {
        const __nv_bfloat16* ab = sA + ks * 16 + ct * 2;
        uint32_t a0 = *(const uint32_t*)(ab + r0 * 72);
        uint32_t a1 = *(const uint32_t*)(ab + (r0 + 8) * 72);
        uint32_t a2 = *(const uint32_t*)(ab + r0 * 72 + 8);
        uint32_t a3 = *(const uint32_t*)(ab + (r0 + 8) * 72 + 8);
#pragma unroll
        for (int nt = 0; nt < 8; nt++) {
            const __nv_bfloat16* bb = sB + (nt * 8 + g) * 72 + ks * 16 + ct * 2;
            uint32_t b0 = *(const uint32_t*)(bb);
            uint32_t b1 = *(const uint32_t*)(bb + 8);
            mma16816(c[nt][0], c[nt][1], c[nt][2], c[nt][3], a0, a1, a2, a3, b0, b1);
        }
    }

    int m0 = node0 + g, m1 = m0 + 8;
    if (mode == 2) {
        int gm0 = clampi(batch[m0], NG);
        int gm1 = clampi(batch[m1], NG);
#pragma unroll
        for (int nt = 0; nt < 8; nt++) {
            int col = nt * 8 + ct * 2;
            float bx = sbias[col], by = sbias[col + 1];
            float v0 = c[nt][0] + bx, v1 = c[nt][1] + by;
            float v2 = c[nt][2] + bx, v3 = c[nt][3] + by;
            if (gm0 == gm1) {
                atomicAdd(&g_pool[gm0 * 64 + col],     v0 + v2);
                atomicAdd(&g_pool[gm0 * 64 + col + 1], v1 + v3);
            } else {
                atomicAdd(&g_pool[gm0 * 64 + col],     v0);
                atomicAdd(&g_pool[gm0 * 64 + col + 1], v1);
                atomicAdd(&g_pool[gm1 * 64 + col],     v2);
                atomicAdd(&g_pool[gm1 * 64 + col + 1], v3);
            }
        }
        return;
    }

    __nv_bfloat162* ob = (dst_sel == 1 ? g_h1b : g_h2b);
#pragma unroll
    for (int nt = 0; nt < 8; nt++) {
        int col = nt * 8 + ct * 2;
        float bx = sbias[col], by = sbias[col + 1];
        float v0 = fmaxf(c[nt][0] + bx, 0.f), v1 = fmaxf(c[nt][1] + by, 0.f);
        float v2 = fmaxf(c[nt][2] + bx, 0.f), v3 = fmaxf(c[nt][3] + by, 0.f);
        ob[m0 * 32 + nt * 4 + ct] = __float22bfloat162_rn(make_float2(v0, v1));
        ob[m1 * 32 + nt * 4 + ct] = __float22bfloat162_rn(make_float2(v2, v3));
    }
}

// ---------------- dense + bias + softmax-threshold ----------------
__global__ __launch_bounds__(256) void k_dense(const float* __restrict__ Wd,
                                               const float* __restrict__ bd,
                                               float* __restrict__ out) {
    __shared__ float sp[4 * 64];
    __shared__ float sred[256];
    int tid = threadIdx.x;
    int g0 = blockIdx.x * 4;

    {   // mean pool into shared
        int r = tid >> 6, f = tid & 63;
        int c = g_cnt[g0 + r];
        if (c < 1) c = 1;
        sp[tid] = g_pool[(g0 + r) * 64 + f] / (float)c;
    }
    __syncthreads();

    float acc[4][8];
#pragma unroll
    for (int r = 0; r < 4; r++)
#pragma unroll
        for (int j = 0; j < 8; j++) acc[r][j] = 0.f;

#pragma unroll 4
    for (int k = 0; k < 64; k++) {
        float p0 = sp[0 * 64 + k], p1 = sp[1 * 64 + k];
        float p2 = sp[2 * 64 + k], p3 = sp[3 * 64 + k];
#pragma unroll
        for (int j = 0; j < 8; j++) {
            float w = Wd[k * NB + tid + 256 * j];
            acc[0][j] += p0 * w;
            acc[1][j] += p1 * w;
            acc[2][j] += p2 * w;
            acc[3][j] += p3 * w;
        }
    }
#pragma unroll
    for (int j = 0; j < 8; j++) {
        float bb = bd[tid + 256 * j];
        acc[0][j] += bb; acc[1][j] += bb; acc[2][j] += bb; acc[3][j] += bb;
    }

    for (int r = 0; r < 4; r++) {
        float m = -3.402823466e38f;
#pragma unroll
        for (int j = 0; j < 8; j++) m = fmaxf(m, acc[r][j]);
        sred[tid] = m;
        __syncthreads();
        for (int s = 128; s > 0; s >>= 1) {
            if (tid < s) sred[tid] = fmaxf(sred[tid], sred[tid + s]);
            __syncthreads();
        }
        float rowmax = sred[0];
        __syncthreads();

        float s = 0.f;
#pragma unroll
        for (int j = 0; j < 8; j++) s += expf(acc[r][j] - rowmax);
        sred[tid] = s;
        __syncthreads();
        for (int st = 128; st > 0; st >>= 1) {
            if (tid < st) sred[tid] += sred[tid + st];
            __syncthreads();
        }
        float thr = 0.5f * sred[0];
        __syncthreads();

#pragma unroll
        for (int j = 0; j < 8; j++) {
            int col = tid + 256 * j;
            out[(size_t)(g0 + r) * NB + col] =
                (expf(acc[r][j] - rowmax) >= thr) ? 1.0f : 0.0f;
        }
    }
}

// ---------------- launch ----------------
extern "C" void kernel_launch(void* const* d_in, const int* in_sizes, int n_in,
                              void* d_out, int out_size) {
    const float* x      = (const float*)d_in[0];
    const int*   ei     = (const int*)d_in[1];     // int32
    const int*   bat    = (const int*)d_in[2];     // int32
    const float* W1 = (const float*)d_in[3];
    const float* b1 = (const float*)d_in[4];
    const float* W2 = (const float*)d_in[5];
    const float* b2 = (const float*)d_in[6];
    const float* W3 = (const float*)d_in[7];
    const float* b3 = (const float*)d_in[8];
    const float* Wd = (const float*)d_in[9];
    const float* bd = (const float*)d_in[10];
    float* out = (float*)d_out;

    const int AGG_BLOCKS  = (N_NODES * 32 + 255) / 256;   // warp per node
    const int MMA_BLOCKS  = (N_NODES + 127) / 128;        // 782

    k_zero_xb<<<512, 256>>>(x);                           // launch 1
    k_hist<<<1024, 256>>>(ei);                            // launch 2
    k_scan1<<<NBLK, 1024>>>();                            // launch 3

    // launch 4 — PROFILING PROBE: agg pass over g_xb. On the first-ever call
    // g_rowoff holds scan1's block-local partial offsets (beg<=end in-block,
    // csr zero-initialized -> all reads in-bounds, near-zero work). On capture
    // and every timed replay, g_csr/g_deg persist from the previous invocation
    // -> the probe runs a full-size real-distribution aggregation. Its output
    // g_aggb is overwritten by the real k_agg(0) below, so the final result is
    // unchanged and deterministic. dur_us delta vs R12 = one agg layer; ncu
    // (which samples launch #4) profiles it.
    k_agg<<<AGG_BLOCKS, 256>>>(0);

    k_scan2<<<1, 128>>>();                                // launch 5
    k_scan3<<<(N_NODES + 255) / 256, 256>>>(bat);         // launch 6
    k_scatter<<<(N_EDGES / 4 + 255) / 256, 256>>>(ei);    // launch 7

    // layer 1: agg(xb) -> mma gemm (+ReLU) -> h1b
    k_agg<<<AGG_BLOCKS, 256>>>(0);
    k_gemm_mma<<<MMA_BLOCKS, 256>>>(W1, b1, bat, 0, 1);
    // layer 2: agg(h1b) -> mma gemm (+ReLU) -> h2b
    k_agg<<<AGG_BLOCKS, 256>>>(1);
    k_gemm_mma<<<MMA_BLOCKS, 256>>>(W2, b2, bat, 0, 2);
    // layer 3: agg(h2b) -> mma gemm (+pool epilogue)
    k_agg<<<AGG_BLOCKS, 256>>>(2);
    k_gemm_mma<<<MMA_BLOCKS, 256>>>(W3, b3, bat, 2, 0);

    // dense/softmax/threshold
    k_dense<<<NG / 4, 256>>>(Wd, bd, out);
}

// round 14
// speedup vs baseline: 702.5987x; 702.5987x over previous
#include <cuda_runtime.h>
#include <cuda_bf16.h>
#include <cstdint>

#define N_NODES 100000
#define N_EDGES 1600000
#define NF      64
#define NG      1024
#define NB      2048
#define NBLK    ((N_NODES + 1023) / 1024)   // 98 scan blocks

// ---------------- scratch (static device globals; no allocation) ----------------
__device__ int   g_deg[N_NODES];
__device__ __align__(16) float g_dinv[N_NODES];
__device__ int   g_rowoff[N_NODES + 1];
__device__ int   g_cursor[N_NODES];
__device__ int   g_bsum[NBLK];
__device__ int   g_boff[NBLK];
__device__ __align__(16) int2  g_csr[N_EDGES];               // (src, w as bf16x2 bits)
__device__ __align__(16) __nv_bfloat162 g_aggb[N_NODES * 32]; // agg output (bf16)
__device__ __align__(16) __nv_bfloat162 g_xb [N_NODES * 32];  // x in bf16
__device__ __align__(16) __nv_bfloat162 g_h1b[N_NODES * 32];
__device__ __align__(16) __nv_bfloat162 g_h2b[N_NODES * 32];
__device__ __align__(16) float g_pool[NG * NF];
__device__ int   g_cnt[NG];

__device__ __forceinline__ int clampi(int v, int hi) {
    return v < 0 ? 0 : (v >= hi ? hi - 1 : v);
}
__device__ __forceinline__ __nv_bfloat162 bf2_from_bits(uint32_t u) {
    return *reinterpret_cast<__nv_bfloat162*>(&u);
}
__device__ __forceinline__ uint32_t bits_from_bf2(__nv_bfloat162 v) {
    return *reinterpret_cast<uint32_t*>(&v);
}

// ---------------- zero + x->bf16 (fused, independent work) ----------------
__global__ void k_zero_xb(const float* __restrict__ x) {
    int i = blockIdx.x * blockDim.x + threadIdx.x;
    int stride = gridDim.x * blockDim.x;
    for (int j = i; j < N_NODES; j += stride) g_deg[j] = 0;
    for (int j = i; j < NG * NF; j += stride) g_pool[j] = 0.0f;
    for (int j = i; j < NG; j += stride) g_cnt[j] = 0;
    const float2* x2 = (const float2*)x;
    for (int j = i; j < N_NODES * 32; j += stride)
        g_xb[j] = __float22bfloat162_rn(x2[j]);
}

// histogram: in-degree over dst (int4 vectorized)
__global__ void k_hist(const int* __restrict__ ei) {
    int i = blockIdx.x * blockDim.x + threadIdx.x;
    int stride = gridDim.x * blockDim.x;
    const int4* dst4 = (const int4*)(ei + N_EDGES);
    for (int e = i; e < N_EDGES / 4; e += stride) {
        int4 d = dst4[e];
        atomicAdd(&g_deg[clampi(d.x, N_NODES)], 1);
        atomicAdd(&g_deg[clampi(d.y, N_NODES)], 1);
        atomicAdd(&g_deg[clampi(d.z, N_NODES)], 1);
        atomicAdd(&g_deg[clampi(d.w, N_NODES)], 1);
    }
}

// ---------------- 3-phase parallel scan over g_deg ----------------
__global__ __launch_bounds__(1024) void k_scan1() {
    __shared__ int ssum[1024];
    int t = threadIdx.x;
    int idx = blockIdx.x * 1024 + t;
    int v = (idx < N_NODES) ? g_deg[idx] : 0;
    ssum[t] = v;
    __syncthreads();
    for (int d = 1; d < 1024; d <<= 1) {
        int u = (t >= d) ? ssum[t - d] : 0;
        __syncthreads();
        ssum[t] += u;
        __syncthreads();
    }
    if (idx < N_NODES) g_rowoff[idx] = ssum[t] - v;   // block-local exclusive
    if (t == 1023) g_bsum[blockIdx.x] = ssum[1023];
}

__global__ void k_scan2() {
    __shared__ int s[128];
    int t = threadIdx.x;
    int v = (t < NBLK) ? g_bsum[t] : 0;
    s[t] = v;
    __syncthreads();
    for (int d = 1; d < 128; d <<= 1) {
        int u = (t >= d) ? s[t - d] : 0;
        __syncthreads();
        s[t] += u;
        __syncthreads();
    }
    if (t < NBLK) g_boff[t] = s[t] - v;
    if (t == 127) g_rowoff[N_NODES] = s[127];
}

__global__ void k_scan3(const int* __restrict__ batch) {   // offsets + dinv + graph counts
    int idx = blockIdx.x * blockDim.x + threadIdx.x;
    if (idx < N_NODES) {
        int off = g_rowoff[idx] + g_boff[idx >> 10];
        g_rowoff[idx] = off;
        g_cursor[idx] = off;
        g_dinv[idx] = rsqrtf((float)g_deg[idx] + 1.0f);
        atomicAdd(&g_cnt[clampi(batch[idx], NG)], 1);
    }
}

__global__ void k_scatter(const int* __restrict__ ei) {
    int i = blockIdx.x * blockDim.x + threadIdx.x;
    int stride = gridDim.x * blockDim.x;
    const int4* src4 = (const int4*)ei;
    const int4* dst4 = (const int4*)(ei + N_EDGES);
    for (int e = i; e < N_EDGES / 4; e += stride) {
        int4 sv = src4[e];
        int4 dv = dst4[e];
#define SCAT(SS, DD)                                                    \
        {                                                               \
            int s = clampi(SS, N_NODES);                                \
            int d = clampi(DD, N_NODES);                                \
            int pos = atomicAdd(&g_cursor[d], 1);                       \
            __nv_bfloat16 wb = __float2bfloat16(g_dinv[s] * g_dinv[d]); \
            uint32_t wu = (uint32_t)__bfloat16_as_ushort(wb);           \
            g_csr[pos] = make_int2(s, (int)(wu | (wu << 16)));          \
        }
        SCAT(sv.x, dv.x) SCAT(sv.y, dv.y) SCAT(sv.z, dv.z) SCAT(sv.w, dv.w)
#undef SCAT
    }
}

// ---------------- aggregation: g_aggb[n] = dinv[n]^2*h[n] + sum_e w_e*h[src_e] ----------------
// 4 nodes per warp, 8 lanes per node; lane owns 16B (8 feats); bf16x2 HFMA2 accum
__global__ __launch_bounds__(256) void k_agg(int src_sel) {
    int gw   = (blockIdx.x * blockDim.x + threadIdx.x) >> 5;  // warp id
    int lane = threadIdx.x & 31;
    int sub  = lane >> 3;        // node slot in warp (0..3)
    int sl   = lane & 7;         // 16B segment within node row (0..7)
    int n = gw * 4 + sub;
    if (n >= N_NODES) return;
    const uint4* hb = (const uint4*)(src_sel == 0 ? g_xb
                                   : (src_sel == 1 ? g_h1b : g_h2b));

    float dv = g_dinv[n];
    __nv_bfloat162 sn2 = __float2bfloat162_rn(dv * dv);
    uint4 hv = hb[n * 8 + sl];
    __nv_bfloat162 a0 = __hmul2(sn2, bf2_from_bits(hv.x));
    __nv_bfloat162 a1 = __hmul2(sn2, bf2_from_bits(hv.y));
    __nv_bfloat162 a2 = __hmul2(sn2, bf2_from_bits(hv.z));
    __nv_bfloat162 a3 = __hmul2(sn2, bf2_from_bits(hv.w));

    int beg = g_rowoff[n];
    int end = g_rowoff[n + 1];
    int j = beg;
    for (; j + 2 <= end; j += 2) {
        int2 e0 = g_csr[j], e1 = g_csr[j + 1];
        uint4 v0 = hb[e0.x * 8 + sl];
        uint4 v1 = hb[e1.x * 8 + sl];
        __nv_bfloat162 w0 = bf2_from_bits((uint32_t)e0.y);
        __nv_bfloat162 w1 = bf2_from_bits((uint32_t)e1.y);
        a0 = __hfma2(w0, bf2_from_bits(v0.x), a0);
        a1 = __hfma2(w0, bf2_from_bits(v0.y), a1);
        a2 = __hfma2(w0, bf2_from_bits(v0.z), a2);
        a3 = __hfma2(w0, bf2_from_bits(v0.w), a3);
        a0 = __hfma2(w1, bf2_from_bits(v1.x), a0);
        a1 = __hfma2(w1, bf2_from_bits(v1.y), a1);
        a2 = __hfma2(w1, bf2_from_bits(v1.z), a2);
        a3 = __hfma2(w1, bf2_from_bits(v1.w), a3);
    }
    if (j < end) {
        int2 e = g_csr[j];
        uint4 v = hb[e.x * 8 + sl];
        __nv_bfloat162 w = bf2_from_bits((uint32_t)e.y);
        a0 = __hfma2(w, bf2_from_bits(v.x), a0);
        a1 = __hfma2(w, bf2_from_bits(v.y), a1);
        a2 = __hfma2(w, bf2_from_bits(v.z), a2);
        a3 = __hfma2(w, bf2_from_bits(v.w), a3);
    }
    ((uint4*)g_aggb)[n * 8 + sl] =
        make_uint4(bits_from_bf2(a0), bits_from_bf2(a1),
                   bits_from_bf2(a2), bits_from_bf2(a3));
}

// ---------------- tensor-core GEMM: out = agg @ W + b  (bf16 in, fp32 accum) ----
// block = 256 thr (8 warps); warp computes 16 nodes x 64 cols via mma.m16n8k16.
// mode: 0 = ReLU + bf16 store, 2 = pool atomics epilogue
__device__ __forceinline__ void mma16816(float& c0, float& c1, float& c2, float& c3,
                                         uint32_t a0, uint32_t a1, uint32_t a2, uint32_t a3,
                                         uint32_t b0, uint32_t b1) {
    asm volatile(
        "mma.sync.aligned.m16n8k16.row.col.f32.bf16.bf16.f32 "
        "{%0,%1,%2,%3}, {%4,%5,%6,%7}, {%8,%9}, {%0,%1,%2,%3};\n"
        : "+f"(c0), "+f"(c1), "+f"(c2), "+f"(c3)
        : "r"(a0), "r"(a1), "r"(a2), "r"(a3), "r"(b0), "r"(b1));
}

__global__ __launch_bounds__(256) void k_gemm_mma(const float* __restrict__ W,
                                                  const float* __restrict__ b,
                                                  const int* __restrict__ batch,
                                                  int mode, int dst_sel) {
    __shared__ __nv_bfloat16 sA[128 * 72];   // 128 nodes x 64 feats, pitch 72
    __shared__ __nv_bfloat16 sB[64 * 72];    // W^T: sB[n][k], pitch 72
    __shared__ float sbias[64];
    int tid = threadIdx.x;

    // stage W^T (bf16) and bias
    for (int i = tid; i < 64 * 64; i += 256) {
        int k = i >> 6, n = i & 63;
        sB[n * 72 + k] = __float2bfloat16(W[i]);
    }
    if (tid < 64) sbias[tid] = b[tid];

    // stage A tile: 128 node rows x 128B, int4 cooperative
    int node_base = blockIdx.x * 128;
    const int4* src = (const int4*)g_aggb;
    for (int i = tid; i < 128 * 8; i += 256) {
        int row = i >> 3, seg = i & 7;
        int node = node_base + row;
        int4 v = make_int4(0, 0, 0, 0);
        if (node < N_NODES) v = src[node * 8 + seg];
        *(int4*)(sA + row * 72 + seg * 8) = v;   // 144B pitch, 16B aligned
    }
    __syncthreads();

    int warp = tid >> 5, lane = tid & 31;
    int node0 = node_base + warp * 16;
    if (node0 >= N_NODES) return;   // N_NODES % 16 == 0: warps fully valid or invalid
    int g = lane >> 2, ct = lane & 3;

    float c[8][4];
#pragma unroll
    for (int nt = 0; nt < 8; nt++)
#pragma unroll
        for (int q = 0; q < 4; q++) c[nt][q] = 0.f;

    int r0 = warp * 16 + g;
#pragma unroll
    for (int ks = 0; ks < 4; ks++) {
        const __nv_bfloat16* ab = sA + ks * 16 + ct * 2;
        uint32_t a0 = *(const uint32_t*)(ab + r0 * 72);
        uint32_t a1 = *(const uint32_t*)(ab + (r0 + 8) * 72);
        uint32_t a2 = *(const uint32_t*)(ab + r0 * 72 + 8);
        uint32_t a3 = *(const uint32_t*)(ab + (r0 + 8) * 72 + 8);
#pragma unroll
        for (int nt = 0; nt < 8; nt++) {
            const __nv_bfloat16* bb = sB + (nt * 8 + g) * 72 + ks * 16 + ct * 2;
            uint32_t b0 = *(const uint32_t*)(bb);
            uint32_t b1 = *(const uint32_t*)(bb + 8);
            mma16816(c[nt][0], c[nt][1], c[nt][2], c[nt][3], a0, a1, a2, a3, b0, b1);
        }
    }

    int m0 = node0 + g, m1 = m0 + 8;
    if (mode == 2) {
        int gm0 = clampi(batch[m0], NG);
        int gm1 = clampi(batch[m1], NG);
#pragma unroll
        for (int nt = 0; nt < 8; nt++) {
            int col = nt * 8 + ct * 2;
            float bx = sbias[col], by = sbias[col + 1];
            float v0 = c[nt][0] + bx, v1 = c[nt][1] + by;
            float v2 = c[nt][2] + bx, v3 = c[nt][3] + by;
            if (gm0 == gm1) {
                atomicAdd(&g_pool[gm0 * 64 + col],     v0 + v2);
                atomicAdd(&g_pool[gm0 * 64 + col + 1], v1 + v3);
            } else {
                atomicAdd(&g_pool[gm0 * 64 + col],     v0);
                atomicAdd(&g_pool[gm0 * 64 + col + 1], v1);
                atomicAdd(&g_pool[gm1 * 64 + col],     v2);
                atomicAdd(&g_pool[gm1 * 64 + col + 1], v3);
            }
        }
        return;
    }

    __nv_bfloat162* ob = (dst_sel == 1 ? g_h1b : g_h2b);
#pragma unroll
    for (int nt = 0; nt < 8; nt++) {
        int col = nt * 8 + ct * 2;
        float bx = sbias[col], by = sbias[col + 1];
        float v0 = fmaxf(c[nt][0] + bx, 0.f), v1 = fmaxf(c[nt][1] + by, 0.f);
        float v2 = fmaxf(c[nt][2] + bx, 0.f), v3 = fmaxf(c[nt][3] + by, 0.f);
        ob[m0 * 32 + nt * 4 + ct] = __float22bfloat162_rn(make_float2(v0, v1));
        ob[m1 * 32 + nt * 4 + ct] = __float22bfloat162_rn(make_float2(v2, v3));
    }
}

// ---------------- dense + bias + softmax-threshold ----------------
__global__ __launch_bounds__(256) void k_dense(const float* __restrict__ Wd,
                                               const float* __restrict__ bd,
                                               float* __restrict__ out) {
    __shared__ float sp[4 * 64];
    __shared__ float sred[256];
    int tid = threadIdx.x;
    int g0 = blockIdx.x * 4;

    {   // mean pool into shared
        int r = tid >> 6, f = tid & 63;
        int c = g_cnt[g0 + r];
        if (c < 1) c = 1;
        sp[tid] = g_pool[(g0 + r) * 64 + f] / (float)c;
    }
    __syncthreads();

    float acc[4][8];
#pragma unroll
    for (int r = 0; r < 4; r++)
#pragma unroll
        for (int j = 0; j < 8; j++) acc[r][j] = 0.f;

#pragma unroll 4
    for (int k = 0; k < 64; k++) {
        float p0 = sp[0 * 64 + k], p1 = sp[1 * 64 + k];
        float p2 = sp[2 * 64 + k], p3 = sp[3 * 64 + k];
#pragma unroll
        for (int j = 0; j < 8; j++) {
            float w = Wd[k * NB + tid + 256 * j];
            acc[0][j] += p0 * w;
            acc[1][j] += p1 * w;
            acc[2][j] += p2 * w;
            acc[3][j] += p3 * w;
        }
    }
#pragma unroll
    for (int j = 0; j < 8; j++) {
        float bb = bd[tid + 256 * j];
        acc[0][j] += bb; acc[1][j] += bb; acc[2][j] += bb; acc[3][j] += bb;
    }

    for (int r = 0; r < 4; r++) {
        float m = -3.402823466e38f;
#pragma unroll
        for (int j = 0; j < 8; j++) m = fmaxf(m, acc[r][j]);
        sred[tid] = m;
        __syncthreads();
        for (int s = 128; s > 0; s >>= 1) {
            if (tid < s) sred[tid] = fmaxf(sred[tid], sred[tid + s]);
            __syncthreads();
        }
        float rowmax = sred[0];
        __syncthreads();

        float s = 0.f;
#pragma unroll
        for (int j = 0; j < 8; j++) s += expf(acc[r][j] - rowmax);
        sred[tid] = s;
        __syncthreads();
        for (int st = 128; st > 0; st >>= 1) {
            if (tid < st) sred[tid] += sred[tid + st];
            __syncthreads();
        }
        float thr = 0.5f * sred[0];
        __syncthreads();

#pragma unroll
        for (int j = 0; j < 8; j++) {
            int col = tid + 256 * j;
            out[(size_t)(g0 + r) * NB + col] =
                (expf(acc[r][j] - rowmax) >= thr) ? 1.0f : 0.0f;
        }
    }
}

// ---------------- launch ----------------
extern "C" void kernel_launch(void* const* d_in, const int* in_sizes, int n_in,
                              void* d_out, int out_size) {
    const float* x      = (const float*)d_in[0];
    const int*   ei     = (const int*)d_in[1];     // int32
    const int*   bat    = (const int*)d_in[2];     // int32
    const float* W1 = (const float*)d_in[3];
    const float* b1 = (const float*)d_in[4];
    const float* W2 = (const float*)d_in[5];
    const float* b2 = (const float*)d_in[6];
    const float* W3 = (const float*)d_in[7];
    const float* b3 = (const float*)d_in[8];
    const float* Wd = (const float*)d_in[9];
    const float* bd = (const float*)d_in[10];
    float* out = (float*)d_out;

    const int AGG_BLOCKS = (N_NODES / 4 * 32 + 255) / 256;  // 4 nodes/warp -> 3125
    const int MMA_BLOCKS = (N_NODES + 127) / 128;           // 782

    k_zero_xb<<<512, 256>>>(x);
    k_hist<<<1024, 256>>>(ei);
    k_scan1<<<NBLK, 1024>>>();
    k_scan2<<<1, 128>>>();
    k_scan3<<<(N_NODES + 255) / 256, 256>>>(bat);
    k_scatter<<<(N_EDGES / 4 + 255) / 256, 256>>>(ei);

    // layer 1: agg(xb) -> mma gemm (+ReLU) -> h1b
    k_agg<<<AGG_BLOCKS, 256>>>(0);
    k_gemm_mma<<<MMA_BLOCKS, 256>>>(W1, b1, bat, 0, 1);
    // layer 2: agg(h1b) -> mma gemm (+ReLU) -> h2b
    k_agg<<<AGG_BLOCKS, 256>>>(1);
    k_gemm_mma<<<MMA_BLOCKS, 256>>>(W2, b2, bat, 0, 2);
    // layer 3: agg(h2b) -> mma gemm (+pool epilogue)
    k_agg<<<AGG_BLOCKS, 256>>>(2);
    k_gemm_mma<<<MMA_BLOCKS, 256>>>(W3, b3, bat, 2, 0);

    // dense/softmax/threshold
    k_dense<<<NG / 4, 256>>>(Wd, bd, out);
}